// round 6
// baseline (speedup 1.0000x reference)
#include <cuda_runtime.h>
#include <math.h>

#define BB 64
#define TT 2048
#define DD 256
#define MM 20
#define TOPK_N 100

typedef unsigned long long u64;

// ---------- scratch (no allocations allowed) ----------
__device__ float g_center_pred[BB * TT];
__device__ float g_window_pred[BB * TT];
__device__ float g_offset_pred[BB * TT];
__device__ float g_acc[4];          // zero-initialized at load; finalize re-zeros after use
__device__ unsigned int g_ticket;   // ditto

// ---------- fused 3-way GEMV + sigmoid + mask + targets + loss ----------
// 256 threads = 8 warps = 8 rows/block; 256 blocks per batch (grid 2048).
__global__ void proj_loss_kernel(const float* __restrict__ x,
                                 const float* __restrict__ wc, const float* __restrict__ bc,
                                 const float* __restrict__ ww, const float* __restrict__ bw,
                                 const float* __restrict__ wo, const float* __restrict__ bo,
                                 const float* __restrict__ sal,
                                 const float* __restrict__ boundary) {
    __shared__ float s_wc[DD], s_ww[DD], s_wo[DD];
    __shared__ int   s_valid[MM];
    __shared__ int   s_ci[MM];
    __shared__ int   s_rad[MM];
    __shared__ float s_inv[MM];
    __shared__ float s_win[MM];
    __shared__ float s_cfrac[MM];
    __shared__ float s_red[24];

    int tid = threadIdx.x;
    int b = blockIdx.x >> 8;         // 256 blocks per batch
    for (int i = tid; i < DD; i += 256) {
        s_wc[i] = wc[i]; s_ww[i] = ww[i]; s_wo[i] = wo[i];
    }
    if (tid < MM) {
        float b0 = boundary[(b * MM + tid) * 2 + 0];
        float b1 = boundary[(b * MM + tid) * 2 + 1];
        int valid = (b0 != -1.0f);
        float b0c = b0 * 0.5f;
        float b1c = (b1 - 2.0f) * 0.5f;
        float center = fminf((b0c + b1c) * 0.5f, (float)TT - 0.5f);
        float window = b1c - b0c;
        int radius = (int)(window * 0.2f);
        float sigma = ((float)radius + 1.0f) * 0.2f;
        int ci = (int)center;
        s_valid[tid] = valid;
        s_ci[tid]    = ci;
        s_rad[tid]   = radius;
        s_inv[tid]   = 1.0f / (2.0f * sigma * sigma);
        s_win[tid]   = window;
        s_cfrac[tid] = center - (float)ci;
    }
    __syncthreads();

    int w = tid >> 5, lane = tid & 31;
    int row = blockIdx.x * 8 + w;
    int t = row & (TT - 1);
    const float4* xr = reinterpret_cast<const float4*>(x + (size_t)row * DD);
    const float4* w0 = reinterpret_cast<const float4*>(s_wc);
    const float4* w1 = reinterpret_cast<const float4*>(s_ww);
    const float4* w2 = reinterpret_cast<const float4*>(s_wo);

    float sc = 0.f, sw = 0.f, so = 0.f;
#pragma unroll
    for (int c = 0; c < 2; c++) {
        int j = lane + 32 * c;
        float4 v = xr[j];
        float4 a = w0[j];
        sc += v.x * a.x + v.y * a.y + v.z * a.z + v.w * a.w;
        float4 bv = w1[j];
        sw += v.x * bv.x + v.y * bv.y + v.z * bv.z + v.w * bv.w;
        float4 d = w2[j];
        so += v.x * d.x + v.y * d.y + v.z * d.z + v.w * d.w;
    }
#pragma unroll
    for (int o = 16; o; o >>= 1) {
        sc += __shfl_xor_sync(0xffffffffu, sc, o);
        sw += __shfl_xor_sync(0xffffffffu, sw, o);
        so += __shfl_xor_sync(0xffffffffu, so, o);
    }
    float mask = (sal[row] >= 0.f) ? 1.f : 0.f;
    float cp = (1.f / (1.f + expf(-(sc + bc[0])))) * mask;
    float wp = sw + bw[0];
    float op = so + bo[0];
    if (lane == 0) {
        g_center_pred[row] = cp;
        g_window_pred[row] = wp;
        g_offset_pred[row] = op;
    }

    // ---- targets + loss, lane-parallel over the 20 objects ----
    float g = 0.f;
    bool hit = false;
    if (lane < MM && s_valid[lane]) {
        int d = t - s_ci[lane];
        if (abs(d) <= s_rad[lane]) g = expf(-(float)(d * d) * s_inv[lane]);
        hit = (d == 0);
    }
#pragma unroll
    for (int o = 16; o; o >>= 1) g = fmaxf(g, __shfl_xor_sync(0xffffffffu, g, o));
    unsigned bal = __ballot_sync(0xffffffffu, hit);

    float cs = 0.f, wsum = 0.f, osum = 0.f;
    if (lane == 0) {
        float ct = g;
        float pos = (ct == 1.0f) ? 1.f : 0.f;
        float omc = 1.f - cp;
        float pl = -logf(cp + 1e-12f) * omc * omc * pos;
        float omt = 1.f - ct;
        float o2 = omt * omt;
        float nl = -logf(omc + 1e-12f) * cp * cp * (o2 * o2);
        cs = (pl + nl) * mask;
        if (bal) {
            int last = 31 - __clz(bal);      // last valid object with ci==t wins
            wsum = fabsf(wp - s_win[last]);
            osum = fabsf(op - s_cfrac[last]);
        }
        s_red[w] = cs; s_red[8 + w] = wsum; s_red[16 + w] = osum;
    }
    __syncthreads();
    if (tid < 8) {
        // reduce the 8 warp partials with one warp (lanes 0..7 hold values)
        float a = s_red[tid], b2 = s_red[8 + tid], c2 = s_red[16 + tid];
#pragma unroll
        for (int o = 4; o; o >>= 1) {
            a  += __shfl_xor_sync(0xffu, a, o);
            b2 += __shfl_xor_sync(0xffu, b2, o);
            c2 += __shfl_xor_sync(0xffu, c2, o);
        }
        if (tid == 0) {
            atomicAdd(&g_acc[0], a);
            atomicAdd(&g_acc[1], b2);
            atomicAdd(&g_acc[2], c2);
        }
    }
    // avg_factor: one block per batch counts valid objects
    if ((blockIdx.x & 255) == 0 && w == 0) {
        unsigned vb = __ballot_sync(0xffffffffu, lane < MM && s_valid[lane]);
        if (lane == 0) atomicAdd(&g_acc[3], (float)__popc(vb));
    }
}

// bitonic compare-exchange via warp shuffle (j <= 16); i = element index, k = block size
__device__ __forceinline__ u64 bshfl(u64 v, int i, int j, int k) {
    u64 pv = __shfl_xor_sync(0xffffffffu, v, j);
    bool lower = ((i & j) == 0);
    bool up = ((i & k) == 0);
    u64 mx = v > pv ? v : pv;
    u64 mn = v > pv ? pv : v;
    return (lower == up) ? mx : mn;
}

// in-thread compare-exchange; up => larger value to lower index (descending)
__device__ __forceinline__ void cxpair(u64& a, u64& b, bool up) {
    u64 mx = a > b ? a : b;
    u64 mn = a > b ? b : a;
    a = up ? mx : mn;
    b = up ? mn : mx;
}

// ---------- NMS + bitonic top-128 + decode + finalize ----------
// One block (512 thr = 16 warps) per batch row; 4 keys/thread in registers.
__global__ void topk_kernel(float* __restrict__ out) {
    __shared__ float s_cp[TT];
    __shared__ u64   s_key[16 * 128];
    __shared__ int   s_last;

    int b = blockIdx.x, tid = threadIdx.x;
    int w = tid >> 5, lane = tid & 31;

    for (int t = tid; t < TT; t += 512) s_cp[t] = g_center_pred[b * TT + t];
    __syncthreads();

    // keys: (f32bits(cpv) << 32) | (T-1-t): desc sort => value desc, index asc
    u64 v[4];
#pragma unroll
    for (int r = 0; r < 4; r++) {
        int i = r * 32 + lane;
        int t = w * 128 + i;
        float c = s_cp[t];
        float l = (t > 0)      ? s_cp[t - 1] : -INFINITY;
        float rr = (t < TT - 1) ? s_cp[t + 1] : -INFINITY;
        float hmax = fmaxf(c, fmaxf(l, rr));
        float cpv = (hmax == c) ? c : 0.f;
        v[r] = ((u64)__float_as_uint(cpv) << 32) | (unsigned int)(TT - 1 - t);
    }

    // full descending bitonic sort of this warp's 128-element run (registers only)
#pragma unroll
    for (int k = 2; k <= 128; k <<= 1) {
#pragma unroll
        for (int j = 64; j > 0; j >>= 1) {
            if (j >= k) continue;
            if (j >= 32) {
                int s = j >> 5;  // 1 or 2
#pragma unroll
                for (int r = 0; r < 4; r++) {
                    if ((r & s) == 0) {
                        int iL = r * 32 + lane;
                        cxpair(v[r], v[r | s], (iL & k) == 0);
                    }
                }
            } else {
#pragma unroll
                for (int r = 0; r < 4; r++) v[r] = bshfl(v[r], r * 32 + lane, j, k);
            }
        }
    }

    // 4 max-merge levels: 16 runs -> exact top-128
    for (int m = 0; m < 4; m++) {
        int h = 1 << m;
        if ((w & (h - 1)) == 0) {
#pragma unroll
            for (int r = 0; r < 4; r++) s_key[w * 128 + r * 32 + lane] = v[r];
        }
        __syncthreads();
        if ((w & (2 * h - 1)) == 0) {
            int p = w + h;
#pragma unroll
            for (int r = 0; r < 4; r++) {
                int i = r * 32 + lane;
                u64 bv = s_key[p * 128 + 127 - i];
                v[r] = v[r] > bv ? v[r] : bv;      // C[i] = max(A[i], B[127-i])
            }
            cxpair(v[0], v[2], true);
            cxpair(v[1], v[3], true);
            cxpair(v[0], v[1], true);
            cxpair(v[2], v[3], true);
#pragma unroll
            for (int j = 16; j > 0; j >>= 1) {
#pragma unroll
                for (int r = 0; r < 4; r++) v[r] = bshfl(v[r], r * 32 + lane, j, 256);
            }
        }
        __syncthreads();
    }
    if (w == 0) {
#pragma unroll
        for (int r = 0; r < 4; r++) s_key[r * 32 + lane] = v[r];
    }
    __syncthreads();

    if (tid < TOPK_N) {
        u64 key = s_key[tid];
        float score = __uint_as_float((unsigned int)(key >> 32));
        int idx = TT - 1 - (int)(key & 0xffffffffu);
        float off = fmaxf(g_offset_pred[b * TT + idx], 0.f);
        float center = (float)idx + off;
        float window = fmaxf(g_window_pred[b * TT + idx], 0.f);
        float lo = fminf(fmaxf(center - window * 0.5f, 0.f), (float)(TT - 1)) * 2.0f;
        float hi = fminf(fmaxf(center + window * 0.5f, 0.f), (float)(TT - 1)) * 2.0f + 2.0f;
        float* o = out + ((size_t)b * TOPK_N + tid) * 3;
        o[0] = lo; o[1] = hi; o[2] = score;
    }

    // ---- finalize: last block writes losses, then resets accumulators ----
    __syncthreads();
    if (tid == 0) {
        __threadfence();
        unsigned int old = atomicAdd(&g_ticket, 1u);
        s_last = (old == BB - 1) ? 1 : 0;
    }
    __syncthreads();
    if (s_last && tid == 0) {
        __threadfence();
        float avg = g_acc[3];
        out[BB * TOPK_N * 3 + 0] = g_acc[0] / avg;
        out[BB * TOPK_N * 3 + 1] = 0.1f * g_acc[1] / avg;
        out[BB * TOPK_N * 3 + 2] = g_acc[2] / avg;
        g_acc[0] = 0.f; g_acc[1] = 0.f; g_acc[2] = 0.f; g_acc[3] = 0.f;
        g_ticket = 0;   // leave state zeroed for the next (graph-replayed) run
    }
}

extern "C" void kernel_launch(void* const* d_in, const int* in_sizes, int n_in,
                              void* d_out, int out_size) {
    const float* x        = (const float*)d_in[0];
    const float* w_center = (const float*)d_in[1];
    const float* b_center = (const float*)d_in[2];
    const float* w_window = (const float*)d_in[3];
    const float* b_window = (const float*)d_in[4];
    const float* w_offset = (const float*)d_in[5];
    const float* b_offset = (const float*)d_in[6];
    const float* saliency = (const float*)d_in[7];
    const float* boundary = (const float*)d_in[8];
    float* out = (float*)d_out;

    proj_loss_kernel<<<(BB * TT) / 8, 256>>>(x, w_center, b_center, w_window, b_window,
                                             w_offset, b_offset, saliency, boundary);
    topk_kernel<<<BB, 512>>>(out);
}

// round 8
// speedup vs baseline: 1.4288x; 1.4288x over previous
#include <cuda_runtime.h>
#include <math.h>

#define BB 64
#define TT 2048
#define DD 256
#define MM 20
#define TOPK_N 100
#define PROJ_BLOCKS 8192          // (BB*TT)/16 rows per block
#define BLK_PER_BATCH 128

typedef unsigned long long u64;

// ---------- scratch (no allocations allowed) ----------
__device__ float g_center_pred[BB * TT];
__device__ float g_window_pred[BB * TT];
__device__ float g_offset_pred[BB * TT];
__device__ float g_part[3 * PROJ_BLOCKS];   // per-block loss partials (planes)
__device__ float g_acc[4];                  // zero-init; finalize re-zeros after use
__device__ unsigned int g_ticket;           // ditto

// ---------- fused 3-way GEMV + sigmoid + mask + targets + loss ----------
// 512 threads = 16 warps = 16 rows/block; 128 blocks per batch.
__global__ void __launch_bounds__(512) proj_loss_kernel(
        const float* __restrict__ x,
        const float* __restrict__ wc, const float* __restrict__ bc,
        const float* __restrict__ ww, const float* __restrict__ bw,
        const float* __restrict__ wo, const float* __restrict__ bo,
        const float* __restrict__ sal,
        const float* __restrict__ boundary) {
    __shared__ float s_wc[DD], s_ww[DD], s_wo[DD];
    __shared__ int   s_valid[MM];
    __shared__ int   s_ci[MM];
    __shared__ int   s_rad[MM];
    __shared__ float s_inv[MM];
    __shared__ float s_win[MM];
    __shared__ float s_cfrac[MM];
    __shared__ float s_red[48];

    int tid = threadIdx.x;
    int b = blockIdx.x >> 7;         // 128 blocks per batch
    for (int i = tid; i < DD; i += 512) {
        s_wc[i] = wc[i]; s_ww[i] = ww[i]; s_wo[i] = wo[i];
    }
    if (tid < MM) {
        float b0 = boundary[(b * MM + tid) * 2 + 0];
        float b1 = boundary[(b * MM + tid) * 2 + 1];
        int valid = (b0 != -1.0f);
        float b0c = b0 * 0.5f;
        float b1c = (b1 - 2.0f) * 0.5f;
        float center = fminf((b0c + b1c) * 0.5f, (float)TT - 0.5f);
        float window = b1c - b0c;
        int radius = (int)(window * 0.2f);
        float sigma = ((float)radius + 1.0f) * 0.2f;
        int ci = (int)center;
        s_valid[tid] = valid;
        s_ci[tid]    = ci;
        s_rad[tid]   = radius;
        s_inv[tid]   = 1.0f / (2.0f * sigma * sigma);
        s_win[tid]   = window;
        s_cfrac[tid] = center - (float)ci;
    }
    __syncthreads();

    int w = tid >> 5, lane = tid & 31;
    int row = blockIdx.x * 16 + w;
    int t = row & (TT - 1);
    const float4* xr = reinterpret_cast<const float4*>(x + (size_t)row * DD);
    const float4* w0 = reinterpret_cast<const float4*>(s_wc);
    const float4* w1 = reinterpret_cast<const float4*>(s_ww);
    const float4* w2 = reinterpret_cast<const float4*>(s_wo);

    // front-batch both global loads, then FMA
    float4 v0 = xr[lane];
    float4 v1 = xr[lane + 32];

    float4 a0 = w0[lane], a1 = w0[lane + 32];
    float sc = v0.x * a0.x + v0.y * a0.y + v0.z * a0.z + v0.w * a0.w
             + v1.x * a1.x + v1.y * a1.y + v1.z * a1.z + v1.w * a1.w;
    float4 b0v = w1[lane], b1v = w1[lane + 32];
    float sw = v0.x * b0v.x + v0.y * b0v.y + v0.z * b0v.z + v0.w * b0v.w
             + v1.x * b1v.x + v1.y * b1v.y + v1.z * b1v.z + v1.w * b1v.w;
    float4 c0 = w2[lane], c1 = w2[lane + 32];
    float so = v0.x * c0.x + v0.y * c0.y + v0.z * c0.z + v0.w * c0.w
             + v1.x * c1.x + v1.y * c1.y + v1.z * c1.z + v1.w * c1.w;

#pragma unroll
    for (int o = 16; o; o >>= 1) {
        sc += __shfl_xor_sync(0xffffffffu, sc, o);
        sw += __shfl_xor_sync(0xffffffffu, sw, o);
        so += __shfl_xor_sync(0xffffffffu, so, o);
    }
    float mask = (sal[row] >= 0.f) ? 1.f : 0.f;
    float cp = (1.f / (1.f + expf(-(sc + bc[0])))) * mask;
    float wp = sw + bw[0];
    float op = so + bo[0];
    if (lane == 0) {
        g_center_pred[row] = cp;
        g_window_pred[row] = wp;
        g_offset_pred[row] = op;
    }

    // ---- targets + loss, lane-parallel over the 20 objects ----
    float g = 0.f;
    bool hit = false;
    if (lane < MM && s_valid[lane]) {
        int d = t - s_ci[lane];
        if (abs(d) <= s_rad[lane]) g = expf(-(float)(d * d) * s_inv[lane]);
        hit = (d == 0);
    }
#pragma unroll
    for (int o = 16; o; o >>= 1) g = fmaxf(g, __shfl_xor_sync(0xffffffffu, g, o));
    unsigned bal = __ballot_sync(0xffffffffu, hit);

    if (lane == 0) {
        float ct = g;
        float pos = (ct == 1.0f) ? 1.f : 0.f;
        float omc = 1.f - cp;
        float pl = -logf(cp + 1e-12f) * omc * omc * pos;
        float omt = 1.f - ct;
        float o2 = omt * omt;
        float nl = -logf(omc + 1e-12f) * cp * cp * (o2 * o2);
        float cs = (pl + nl) * mask;
        float wsum = 0.f, osum = 0.f;
        if (bal) {
            int last = 31 - __clz(bal);      // last valid object with ci==t wins
            wsum = fabsf(wp - s_win[last]);
            osum = fabsf(op - s_cfrac[last]);
        }
        s_red[w] = cs; s_red[16 + w] = wsum; s_red[32 + w] = osum;
    }
    __syncthreads();
    if (tid < 16) {
        float a = s_red[tid], b2 = s_red[16 + tid], c2 = s_red[32 + tid];
#pragma unroll
        for (int o = 8; o; o >>= 1) {
            a  += __shfl_xor_sync(0xffffu, a, o);
            b2 += __shfl_xor_sync(0xffffu, b2, o);
            c2 += __shfl_xor_sync(0xffffu, c2, o);
        }
        if (tid == 0) {       // plain stores: no atomic contention
            g_part[blockIdx.x]                   = a;
            g_part[PROJ_BLOCKS + blockIdx.x]     = b2;
            g_part[2 * PROJ_BLOCKS + blockIdx.x] = c2;
        }
    }
    // avg_factor: one block per batch counts valid objects (64 atomics total)
    if ((blockIdx.x & (BLK_PER_BATCH - 1)) == 0 && w == 0) {
        unsigned vb = __ballot_sync(0xffffffffu, lane < MM && s_valid[lane]);
        if (lane == 0) atomicAdd(&g_acc[3], (float)__popc(vb));
    }
}

// bitonic compare-exchange via warp shuffle (j <= 16); i = element index, k = block size
__device__ __forceinline__ u64 bshfl(u64 v, int i, int j, int k) {
    u64 pv = __shfl_xor_sync(0xffffffffu, v, j);
    bool lower = ((i & j) == 0);
    bool up = ((i & k) == 0);
    u64 mx = v > pv ? v : pv;
    u64 mn = v > pv ? pv : v;
    return (lower == up) ? mx : mn;
}

// in-thread compare-exchange; up => larger value to lower index (descending)
__device__ __forceinline__ void cxpair(u64& a, u64& b, bool up) {
    u64 mx = a > b ? a : b;
    u64 mn = a > b ? b : a;
    a = up ? mx : mn;
    b = up ? mn : mx;
}

// ---------- loss-partial reduce + NMS + bitonic top-128 + decode + finalize ----------
// One block (512 thr = 16 warps) per batch row; 4 keys/thread in registers.
__global__ void __launch_bounds__(512) topk_kernel(float* __restrict__ out) {
    __shared__ float s_cp[TT];
    __shared__ u64   s_key[16 * 128];
    __shared__ float s_red[12];
    __shared__ int   s_last;

    int b = blockIdx.x, tid = threadIdx.x;
    int w = tid >> 5, lane = tid & 31;

    // coalesced float4 load of this batch's cp row
    {
        const float4* src = reinterpret_cast<const float4*>(g_center_pred + b * TT);
        reinterpret_cast<float4*>(s_cp)[tid] = src[tid];
    }
    // reduce this batch's loss partials (threads 0..127), overlapped with cp load
    if (tid < BLK_PER_BATCH) {
        int base = b * BLK_PER_BATCH + tid;
        float a  = g_part[base];
        float b2 = g_part[PROJ_BLOCKS + base];
        float c2 = g_part[2 * PROJ_BLOCKS + base];
#pragma unroll
        for (int o = 16; o; o >>= 1) {
            a  += __shfl_xor_sync(0xffffffffu, a, o);
            b2 += __shfl_xor_sync(0xffffffffu, b2, o);
            c2 += __shfl_xor_sync(0xffffffffu, c2, o);
        }
        if (lane == 0) { s_red[w] = a; s_red[4 + w] = b2; s_red[8 + w] = c2; }
    }
    __syncthreads();
    if (tid == 0) {
        float a = s_red[0] + s_red[1] + s_red[2] + s_red[3];
        float b2 = s_red[4] + s_red[5] + s_red[6] + s_red[7];
        float c2 = s_red[8] + s_red[9] + s_red[10] + s_red[11];
        atomicAdd(&g_acc[0], a);
        atomicAdd(&g_acc[1], b2);
        atomicAdd(&g_acc[2], c2);
    }

    // keys: (f32bits(cpv) << 32) | (T-1-t): desc sort => value desc, index asc
    u64 v[4];
#pragma unroll
    for (int r = 0; r < 4; r++) {
        int i = r * 32 + lane;
        int t = w * 128 + i;
        float c = s_cp[t];
        float l = (t > 0)      ? s_cp[t - 1] : -INFINITY;
        float rr = (t < TT - 1) ? s_cp[t + 1] : -INFINITY;
        float hmax = fmaxf(c, fmaxf(l, rr));
        float cpv = (hmax == c) ? c : 0.f;
        v[r] = ((u64)__float_as_uint(cpv) << 32) | (unsigned int)(TT - 1 - t);
    }

    // full descending bitonic sort of this warp's 128-element run (registers only)
#pragma unroll
    for (int k = 2; k <= 128; k <<= 1) {
#pragma unroll
        for (int j = 64; j > 0; j >>= 1) {
            if (j >= k) continue;
            if (j >= 32) {
                int s = j >> 5;  // 1 or 2
#pragma unroll
                for (int r = 0; r < 4; r++) {
                    if ((r & s) == 0) {
                        int iL = r * 32 + lane;
                        cxpair(v[r], v[r | s], (iL & k) == 0);
                    }
                }
            } else {
#pragma unroll
                for (int r = 0; r < 4; r++) v[r] = bshfl(v[r], r * 32 + lane, j, k);
            }
        }
    }

    // 4 max-merge levels: 16 runs -> exact top-128
    for (int m = 0; m < 4; m++) {
        int h = 1 << m;
        if ((w & (h - 1)) == 0) {
#pragma unroll
            for (int r = 0; r < 4; r++) s_key[w * 128 + r * 32 + lane] = v[r];
        }
        __syncthreads();
        if ((w & (2 * h - 1)) == 0) {
            int p = w + h;
#pragma unroll
            for (int r = 0; r < 4; r++) {
                int i = r * 32 + lane;
                u64 bv = s_key[p * 128 + 127 - i];
                v[r] = v[r] > bv ? v[r] : bv;      // C[i] = max(A[i], B[127-i])
            }
            cxpair(v[0], v[2], true);
            cxpair(v[1], v[3], true);
            cxpair(v[0], v[1], true);
            cxpair(v[2], v[3], true);
#pragma unroll
            for (int j = 16; j > 0; j >>= 1) {
#pragma unroll
                for (int r = 0; r < 4; r++) v[r] = bshfl(v[r], r * 32 + lane, j, 256);
            }
        }
        __syncthreads();
    }
    if (w == 0) {
#pragma unroll
        for (int r = 0; r < 4; r++) s_key[r * 32 + lane] = v[r];
    }
    __syncthreads();

    if (tid < TOPK_N) {
        u64 key = s_key[tid];
        float score = __uint_as_float((unsigned int)(key >> 32));
        int idx = TT - 1 - (int)(key & 0xffffffffu);
        float off = fmaxf(g_offset_pred[b * TT + idx], 0.f);
        float center = (float)idx + off;
        float window = fmaxf(g_window_pred[b * TT + idx], 0.f);
        float lo = fminf(fmaxf(center - window * 0.5f, 0.f), (float)(TT - 1)) * 2.0f;
        float hi = fminf(fmaxf(center + window * 0.5f, 0.f), (float)(TT - 1)) * 2.0f + 2.0f;
        float* o = out + ((size_t)b * TOPK_N + tid) * 3;
        o[0] = lo; o[1] = hi; o[2] = score;
    }

    // ---- finalize: last block writes losses, then resets accumulators ----
    __syncthreads();
    if (tid == 0) {
        __threadfence();
        unsigned int old = atomicAdd(&g_ticket, 1u);
        s_last = (old == BB - 1) ? 1 : 0;
    }
    __syncthreads();
    if (s_last && tid == 0) {
        __threadfence();
        float avg = g_acc[3];
        out[BB * TOPK_N * 3 + 0] = g_acc[0] / avg;
        out[BB * TOPK_N * 3 + 1] = 0.1f * g_acc[1] / avg;
        out[BB * TOPK_N * 3 + 2] = g_acc[2] / avg;
        g_acc[0] = 0.f; g_acc[1] = 0.f; g_acc[2] = 0.f; g_acc[3] = 0.f;
        g_ticket = 0;   // leave state zeroed for the next (graph-replayed) run
    }
}

extern "C" void kernel_launch(void* const* d_in, const int* in_sizes, int n_in,
                              void* d_out, int out_size) {
    const float* x        = (const float*)d_in[0];
    const float* w_center = (const float*)d_in[1];
    const float* b_center = (const float*)d_in[2];
    const float* w_window = (const float*)d_in[3];
    const float* b_window = (const float*)d_in[4];
    const float* w_offset = (const float*)d_in[5];
    const float* b_offset = (const float*)d_in[6];
    const float* saliency = (const float*)d_in[7];
    const float* boundary = (const float*)d_in[8];
    float* out = (float*)d_out;

    proj_loss_kernel<<<PROJ_BLOCKS, 512>>>(x, w_center, b_center, w_window, b_window,
                                           w_offset, b_offset, saliency, boundary);
    topk_kernel<<<BB, 512>>>(out);
}

// round 9
// speedup vs baseline: 1.9819x; 1.3871x over previous
#include <cuda_runtime.h>
#include <math.h>

#define BB 64
#define TT 2048
#define DD 256
#define MM 20
#define TOPK_N 100

typedef unsigned long long u64;

// ---------- scratch (no allocations allowed) ----------
__device__ float g_center_pred[BB * TT];
__device__ float g_window_pred[BB * TT];
__device__ float g_offset_pred[BB * TT];
__device__ float g_acc[4];          // zero-init; finalize re-zeros after use
__device__ unsigned int g_ticket;   // ditto

// ---------- pure 3-way GEMV + sigmoid + mask ----------
// 256 threads = 8 warps; each warp handles TWO adjacent rows (MLP=4 front-batched
// LDG.128 per lane). 16 rows/block -> grid 8192.
__global__ void __launch_bounds__(256) proj_kernel(
        const float* __restrict__ x,
        const float* __restrict__ wc, const float* __restrict__ bc,
        const float* __restrict__ ww, const float* __restrict__ bw,
        const float* __restrict__ wo, const float* __restrict__ bo,
        const float* __restrict__ sal) {
    __shared__ float s_w[3 * DD];
    int tid = threadIdx.x;
    for (int i = tid; i < 3 * DD; i += 256) {
        s_w[i] = (i < DD) ? wc[i] : (i < 2 * DD) ? ww[i - DD] : wo[i - 2 * DD];
    }
    __syncthreads();

    int w = tid >> 5, lane = tid & 31;
    size_t pair = (size_t)blockIdx.x * 8 + w;
    size_t row0 = pair * 2, row1 = row0 + 1;
    const float4* x0 = reinterpret_cast<const float4*>(x + row0 * DD);
    const float4* x1 = reinterpret_cast<const float4*>(x + row1 * DD);
    const float4* w0 = reinterpret_cast<const float4*>(s_w);
    const float4* w1 = reinterpret_cast<const float4*>(s_w + DD);
    const float4* w2 = reinterpret_cast<const float4*>(s_w + 2 * DD);

    // front-batch all 4 global loads
    float4 p0 = x0[lane];
    float4 p1 = x0[lane + 32];
    float4 q0 = x1[lane];
    float4 q1 = x1[lane + 32];

    float4 a0 = w0[lane], a1 = w0[lane + 32];
    float4 b0 = w1[lane], b1 = w1[lane + 32];
    float4 c0 = w2[lane], c1 = w2[lane + 32];

    float sc0 = p0.x*a0.x + p0.y*a0.y + p0.z*a0.z + p0.w*a0.w
              + p1.x*a1.x + p1.y*a1.y + p1.z*a1.z + p1.w*a1.w;
    float sw0 = p0.x*b0.x + p0.y*b0.y + p0.z*b0.z + p0.w*b0.w
              + p1.x*b1.x + p1.y*b1.y + p1.z*b1.z + p1.w*b1.w;
    float so0 = p0.x*c0.x + p0.y*c0.y + p0.z*c0.z + p0.w*c0.w
              + p1.x*c1.x + p1.y*c1.y + p1.z*c1.z + p1.w*c1.w;
    float sc1 = q0.x*a0.x + q0.y*a0.y + q0.z*a0.z + q0.w*a0.w
              + q1.x*a1.x + q1.y*a1.y + q1.z*a1.z + q1.w*a1.w;
    float sw1 = q0.x*b0.x + q0.y*b0.y + q0.z*b0.z + q0.w*b0.w
              + q1.x*b1.x + q1.y*b1.y + q1.z*b1.z + q1.w*b1.w;
    float so1 = q0.x*c0.x + q0.y*c0.y + q0.z*c0.z + q0.w*c0.w
              + q1.x*c1.x + q1.y*c1.y + q1.z*c1.z + q1.w*c1.w;

#pragma unroll
    for (int o = 16; o; o >>= 1) {
        sc0 += __shfl_xor_sync(0xffffffffu, sc0, o);
        sw0 += __shfl_xor_sync(0xffffffffu, sw0, o);
        so0 += __shfl_xor_sync(0xffffffffu, so0, o);
        sc1 += __shfl_xor_sync(0xffffffffu, sc1, o);
        sw1 += __shfl_xor_sync(0xffffffffu, sw1, o);
        so1 += __shfl_xor_sync(0xffffffffu, so1, o);
    }
    // after butterfly all lanes hold the sums: lane 0 writes row0, lane 1 row1
    if (lane == 0) {
        float mask = (sal[row0] >= 0.f) ? 1.f : 0.f;
        g_center_pred[row0] = (1.f / (1.f + expf(-(sc0 + bc[0])))) * mask;
        g_window_pred[row0] = sw0 + bw[0];
        g_offset_pred[row0] = so0 + bo[0];
    } else if (lane == 1) {
        float mask = (sal[row1] >= 0.f) ? 1.f : 0.f;
        g_center_pred[row1] = (1.f / (1.f + expf(-(sc1 + bc[0])))) * mask;
        g_window_pred[row1] = sw1 + bw[0];
        g_offset_pred[row1] = so1 + bo[0];
    }
}

// bitonic compare-exchange via warp shuffle (j <= 16); i = element index, k = block size
__device__ __forceinline__ u64 bshfl(u64 v, int i, int j, int k) {
    u64 pv = __shfl_xor_sync(0xffffffffu, v, j);
    bool lower = ((i & j) == 0);
    bool up = ((i & k) == 0);
    u64 mx = v > pv ? v : pv;
    u64 mn = v > pv ? pv : v;
    return (lower == up) ? mx : mn;
}

// in-thread compare-exchange; up => larger value to lower index (descending)
__device__ __forceinline__ void cxpair(u64& a, u64& b, bool up) {
    u64 mx = a > b ? a : b;
    u64 mn = a > b ? b : a;
    a = up ? mx : mn;
    b = up ? mn : mx;
}

// ---------- targets(scatter) + loss + NMS + bitonic top-128 + decode + finalize ----------
// One block (512 thr = 16 warps) per batch row.
__global__ void __launch_bounds__(512) topk_kernel(const float* __restrict__ sal,
                                                   const float* __restrict__ boundary,
                                                   float* __restrict__ out) {
    __shared__ float s_cp[TT];
    __shared__ int   s_ct[TT];           // gaussian target bits (float >= 0)
    __shared__ u64   s_key[16 * 128];
    __shared__ int   s_valid[MM];
    __shared__ int   s_ci[MM];
    __shared__ int   s_rad[MM];
    __shared__ float s_inv[MM];
    __shared__ float s_win[MM];
    __shared__ float s_cfrac[MM];
    __shared__ float s_red[16];
    __shared__ int   s_last;

    int b = blockIdx.x, tid = threadIdx.x;
    int w = tid >> 5, lane = tid & 31;

    // coalesced float4 load of this batch's cp row; zero target plane
    reinterpret_cast<float4*>(s_cp)[tid] =
        reinterpret_cast<const float4*>(g_center_pred + b * TT)[tid];
#pragma unroll
    for (int r = 0; r < 4; r++) s_ct[tid + 512 * r] = 0;

    if (tid < MM) {
        float b0 = boundary[(b * MM + tid) * 2 + 0];
        float b1 = boundary[(b * MM + tid) * 2 + 1];
        int valid = (b0 != -1.0f);
        float b0c = b0 * 0.5f;
        float b1c = (b1 - 2.0f) * 0.5f;
        float center = fminf((b0c + b1c) * 0.5f, (float)TT - 0.5f);
        float window = b1c - b0c;
        int radius = (int)(window * 0.2f);
        float sigma = ((float)radius + 1.0f) * 0.2f;
        int ci = (int)center;
        s_valid[tid] = valid;
        s_ci[tid]    = ci;
        s_rad[tid]   = radius;
        s_inv[tid]   = 1.0f / (2.0f * sigma * sigma);
        s_win[tid]   = window;
        s_cfrac[tid] = center - (float)ci;
    }
    __syncthreads();

    // ---- gaussian scatter-max: 25 threads per object ----
    {
        int obj = tid / 25, sub = tid - obj * 25;
        if (obj < MM && s_valid[obj]) {
            int rad = s_rad[obj], ci = s_ci[obj];
            float inv = s_inv[obj];
            for (int off = -rad + sub; off <= rad; off += 25) {
                int t = ci + off;
                if (t >= 0 && t < TT) {
                    float g = expf(-(float)(off * off) * inv);
                    atomicMax(&s_ct[t], __float_as_int(g));   // valid: g >= 0
                }
            }
        }
    }
    __syncthreads();

    // ---- center loss: one cheap pass over t ----
    float cs = 0.f;
    const float* salb = sal + b * TT;
#pragma unroll
    for (int c = 0; c < 4; c++) {
        int t = tid + 512 * c;
        float ct = __int_as_float(s_ct[t]);
        float mask = (salb[t] >= 0.f) ? 1.f : 0.f;
        float cp = s_cp[t];
        float pos = (ct == 1.0f) ? 1.f : 0.f;
        float omc = 1.f - cp;
        float pl = -logf(cp + 1e-12f) * omc * omc * pos;
        float omt = 1.f - ct;
        float o2 = omt * omt;
        float nl = -logf(omc + 1e-12f) * cp * cp * (o2 * o2);
        cs += (pl + nl) * mask;
    }
#pragma unroll
    for (int o = 16; o; o >>= 1) cs += __shfl_xor_sync(0xffffffffu, cs, o);
    if (lane == 0) s_red[w] = cs;

    // ---- window/offset loss: only the <=20 scatter points (warp 0) ----
    if (w == 0) {
        float ws = 0.f, os = 0.f;
        if (lane < MM && s_valid[lane]) {
            bool isLast = true;
#pragma unroll
            for (int jj = 0; jj < MM; jj++)
                if (jj > lane && s_valid[jj] && s_ci[jj] == s_ci[lane]) isLast = false;
            if (isLast) {   // last-write-wins scatter semantics
                int idx = b * TT + s_ci[lane];
                ws = fabsf(g_window_pred[idx] - s_win[lane]);
                os = fabsf(g_offset_pred[idx] - s_cfrac[lane]);
            }
        }
        unsigned vb = __ballot_sync(0xffffffffu, lane < MM && s_valid[lane]);
#pragma unroll
        for (int o = 16; o; o >>= 1) {
            ws += __shfl_xor_sync(0xffffffffu, ws, o);
            os += __shfl_xor_sync(0xffffffffu, os, o);
        }
        if (lane == 0) {
            atomicAdd(&g_acc[1], ws);
            atomicAdd(&g_acc[2], os);
            atomicAdd(&g_acc[3], (float)__popc(vb));
        }
    }
    __syncthreads();
    if (tid == 0) {
        float a = 0.f;
#pragma unroll
        for (int i = 0; i < 16; i++) a += s_red[i];
        atomicAdd(&g_acc[0], a);
    }

    // ---- NMS keys: (f32bits(cpv) << 32) | (T-1-t) ----
    u64 v[4];
#pragma unroll
    for (int r = 0; r < 4; r++) {
        int i = r * 32 + lane;
        int t = w * 128 + i;
        float c = s_cp[t];
        float l = (t > 0)      ? s_cp[t - 1] : -INFINITY;
        float rr = (t < TT - 1) ? s_cp[t + 1] : -INFINITY;
        float hmax = fmaxf(c, fmaxf(l, rr));
        float cpv = (hmax == c) ? c : 0.f;
        v[r] = ((u64)__float_as_uint(cpv) << 32) | (unsigned int)(TT - 1 - t);
    }

    // full descending bitonic sort of this warp's 128-element run (registers only)
#pragma unroll
    for (int k = 2; k <= 128; k <<= 1) {
#pragma unroll
        for (int j = 64; j > 0; j >>= 1) {
            if (j >= k) continue;
            if (j >= 32) {
                int s = j >> 5;  // 1 or 2
#pragma unroll
                for (int r = 0; r < 4; r++) {
                    if ((r & s) == 0) {
                        int iL = r * 32 + lane;
                        cxpair(v[r], v[r | s], (iL & k) == 0);
                    }
                }
            } else {
#pragma unroll
                for (int r = 0; r < 4; r++) v[r] = bshfl(v[r], r * 32 + lane, j, k);
            }
        }
    }

    // 4 max-merge levels: 16 runs -> exact top-128
    for (int m = 0; m < 4; m++) {
        int h = 1 << m;
        if ((w & (h - 1)) == 0) {
#pragma unroll
            for (int r = 0; r < 4; r++) s_key[w * 128 + r * 32 + lane] = v[r];
        }
        __syncthreads();
        if ((w & (2 * h - 1)) == 0) {
            int p = w + h;
#pragma unroll
            for (int r = 0; r < 4; r++) {
                int i = r * 32 + lane;
                u64 bv = s_key[p * 128 + 127 - i];
                v[r] = v[r] > bv ? v[r] : bv;      // C[i] = max(A[i], B[127-i])
            }
            cxpair(v[0], v[2], true);
            cxpair(v[1], v[3], true);
            cxpair(v[0], v[1], true);
            cxpair(v[2], v[3], true);
#pragma unroll
            for (int j = 16; j > 0; j >>= 1) {
#pragma unroll
                for (int r = 0; r < 4; r++) v[r] = bshfl(v[r], r * 32 + lane, j, 256);
            }
        }
        __syncthreads();
    }
    if (w == 0) {
#pragma unroll
        for (int r = 0; r < 4; r++) s_key[r * 32 + lane] = v[r];
    }
    __syncthreads();

    if (tid < TOPK_N) {
        u64 key = s_key[tid];
        float score = __uint_as_float((unsigned int)(key >> 32));
        int idx = TT - 1 - (int)(key & 0xffffffffu);
        float off = fmaxf(g_offset_pred[b * TT + idx], 0.f);
        float center = (float)idx + off;
        float window = fmaxf(g_window_pred[b * TT + idx], 0.f);
        float lo = fminf(fmaxf(center - window * 0.5f, 0.f), (float)(TT - 1)) * 2.0f;
        float hi = fminf(fmaxf(center + window * 0.5f, 0.f), (float)(TT - 1)) * 2.0f + 2.0f;
        float* o = out + ((size_t)b * TOPK_N + tid) * 3;
        o[0] = lo; o[1] = hi; o[2] = score;
    }

    // ---- finalize: last block writes losses, then resets accumulators ----
    __syncthreads();
    if (tid == 0) {
        __threadfence();
        unsigned int old = atomicAdd(&g_ticket, 1u);
        s_last = (old == BB - 1) ? 1 : 0;
    }
    __syncthreads();
    if (s_last && tid == 0) {
        __threadfence();
        float avg = g_acc[3];
        out[BB * TOPK_N * 3 + 0] = g_acc[0] / avg;
        out[BB * TOPK_N * 3 + 1] = 0.1f * g_acc[1] / avg;
        out[BB * TOPK_N * 3 + 2] = g_acc[2] / avg;
        g_acc[0] = 0.f; g_acc[1] = 0.f; g_acc[2] = 0.f; g_acc[3] = 0.f;
        g_ticket = 0;   // leave state zeroed for the next (graph-replayed) run
    }
}

extern "C" void kernel_launch(void* const* d_in, const int* in_sizes, int n_in,
                              void* d_out, int out_size) {
    const float* x        = (const float*)d_in[0];
    const float* w_center = (const float*)d_in[1];
    const float* b_center = (const float*)d_in[2];
    const float* w_window = (const float*)d_in[3];
    const float* b_window = (const float*)d_in[4];
    const float* w_offset = (const float*)d_in[5];
    const float* b_offset = (const float*)d_in[6];
    const float* saliency = (const float*)d_in[7];
    const float* boundary = (const float*)d_in[8];
    float* out = (float*)d_out;

    proj_kernel<<<(BB * TT) / 16, 256>>>(x, w_center, b_center, w_window, b_window,
                                         w_offset, b_offset, saliency);
    topk_kernel<<<BB, 512>>>(saliency, boundary, out);
}

// round 13
// speedup vs baseline: 1.9832x; 1.0007x over previous
#include <cuda_runtime.h>
#include <math.h>

#define BB 64
#define TT 2048
#define DD 256
#define MM 20
#define TOPK_N 100

typedef unsigned long long u64;

// ---------- scratch (no allocations allowed) ----------
__device__ float g_center_pred[BB * TT];
__device__ float g_window_pred[BB * TT];
__device__ float g_offset_pred[BB * TT];
__device__ float g_acc[4];          // zero-init; finalize re-zeros after use
__device__ unsigned int g_ticket;   // ditto

// ---------- pure 3-way GEMV + sigmoid + mask ----------
// 256 threads = 8 warps; each warp handles TWO adjacent rows (MLP=4 front-batched
// LDG.128 per lane, streaming). 16 rows/block -> grid 8192.
__global__ void __launch_bounds__(256) proj_kernel(
        const float* __restrict__ x,
        const float* __restrict__ wc, const float* __restrict__ bc,
        const float* __restrict__ ww, const float* __restrict__ bw,
        const float* __restrict__ wo, const float* __restrict__ bo,
        const float* __restrict__ sal) {
    __shared__ float s_w[3 * DD];
    int tid = threadIdx.x;
    for (int i = tid; i < 3 * DD; i += 256) {
        s_w[i] = (i < DD) ? wc[i] : (i < 2 * DD) ? ww[i - DD] : wo[i - 2 * DD];
    }
    __syncthreads();

    int w = tid >> 5, lane = tid & 31;
    size_t pair = (size_t)blockIdx.x * 8 + w;
    size_t row0 = pair * 2, row1 = row0 + 1;
    const float4* x0 = reinterpret_cast<const float4*>(x + row0 * DD);
    const float4* x1 = reinterpret_cast<const float4*>(x + row1 * DD);
    const float4* w0 = reinterpret_cast<const float4*>(s_w);
    const float4* w1 = reinterpret_cast<const float4*>(s_w + DD);
    const float4* w2 = reinterpret_cast<const float4*>(s_w + 2 * DD);

    // front-batch all 4 global loads (streaming: x is read exactly once)
    float4 p0 = __ldcs(&x0[lane]);
    float4 p1 = __ldcs(&x0[lane + 32]);
    float4 q0 = __ldcs(&x1[lane]);
    float4 q1 = __ldcs(&x1[lane + 32]);

    float4 a0 = w0[lane], a1 = w0[lane + 32];
    float4 b0 = w1[lane], b1 = w1[lane + 32];
    float4 c0 = w2[lane], c1 = w2[lane + 32];

    float sc0 = p0.x*a0.x + p0.y*a0.y + p0.z*a0.z + p0.w*a0.w
              + p1.x*a1.x + p1.y*a1.y + p1.z*a1.z + p1.w*a1.w;
    float sw0 = p0.x*b0.x + p0.y*b0.y + p0.z*b0.z + p0.w*b0.w
              + p1.x*b1.x + p1.y*b1.y + p1.z*b1.z + p1.w*b1.w;
    float so0 = p0.x*c0.x + p0.y*c0.y + p0.z*c0.z + p0.w*c0.w
              + p1.x*c1.x + p1.y*c1.y + p1.z*c1.z + p1.w*c1.w;
    float sc1 = q0.x*a0.x + q0.y*a0.y + q0.z*a0.z + q0.w*a0.w
              + q1.x*a1.x + q1.y*a1.y + q1.z*a1.z + q1.w*a1.w;
    float sw1 = q0.x*b0.x + q0.y*b0.y + q0.z*b0.z + q0.w*b0.w
              + q1.x*b1.x + q1.y*b1.y + q1.z*b1.z + q1.w*b1.w;
    float so1 = q0.x*c0.x + q0.y*c0.y + q0.z*c0.z + q0.w*c0.w
              + q1.x*c1.x + q1.y*c1.y + q1.z*c1.z + q1.w*c1.w;

#pragma unroll
    for (int o = 16; o; o >>= 1) {
        sc0 += __shfl_xor_sync(0xffffffffu, sc0, o);
        sw0 += __shfl_xor_sync(0xffffffffu, sw0, o);
        so0 += __shfl_xor_sync(0xffffffffu, so0, o);
        sc1 += __shfl_xor_sync(0xffffffffu, sc1, o);
        sw1 += __shfl_xor_sync(0xffffffffu, sw1, o);
        so1 += __shfl_xor_sync(0xffffffffu, so1, o);
    }
    if (lane == 0) {
        float mask = (sal[row0] >= 0.f) ? 1.f : 0.f;
        g_center_pred[row0] = (1.f / (1.f + expf(-(sc0 + bc[0])))) * mask;
        g_window_pred[row0] = sw0 + bw[0];
        g_offset_pred[row0] = so0 + bo[0];
    } else if (lane == 1) {
        float mask = (sal[row1] >= 0.f) ? 1.f : 0.f;
        g_center_pred[row1] = (1.f / (1.f + expf(-(sc1 + bc[0])))) * mask;
        g_window_pred[row1] = sw1 + bw[0];
        g_offset_pred[row1] = so1 + bo[0];
    }
}

// bitonic compare-exchange via warp shuffle (j <= 16); i = element index, k = block size
__device__ __forceinline__ u64 bshfl(u64 v, int i, int j, int k) {
    u64 pv = __shfl_xor_sync(0xffffffffu, v, j);
    bool lower = ((i & j) == 0);
    bool up = ((i & k) == 0);
    u64 mx = v > pv ? v : pv;
    u64 mn = v > pv ? pv : v;
    return (lower == up) ? mx : mn;
}

// in-thread compare-exchange; up => larger value to lower index (descending)
__device__ __forceinline__ void cxpair(u64& a, u64& b, bool up) {
    u64 mx = a > b ? a : b;
    u64 mn = a > b ? b : a;
    a = up ? mx : mn;
    b = up ? mn : mx;
}

// full descending bitonic sort of a 128-run held as v[r] at element r*32+lane
__device__ __forceinline__ void warp_sort128(u64 v[4], int lane) {
#pragma unroll
    for (int k = 2; k <= 128; k <<= 1) {
#pragma unroll
        for (int j = 64; j > 0; j >>= 1) {
            if (j >= k) continue;
            if (j >= 32) {
                int s = j >> 5;  // 1 or 2
#pragma unroll
                for (int r = 0; r < 4; r++) {
                    if ((r & s) == 0) cxpair(v[r], v[r | s], ((r * 32 + lane) & k) == 0);
                }
            } else {
#pragma unroll
                for (int r = 0; r < 4; r++) v[r] = bshfl(v[r], r * 32 + lane, j, k);
            }
        }
    }
}

// descending bitonic merge of a 128 bitonic sequence (after max-combine)
__device__ __forceinline__ void warp_merge128(u64 v[4], int lane) {
    cxpair(v[0], v[2], true);
    cxpair(v[1], v[3], true);
    cxpair(v[0], v[1], true);
    cxpair(v[2], v[3], true);
#pragma unroll
    for (int j = 16; j > 0; j >>= 1) {
#pragma unroll
        for (int r = 0; r < 4; r++) v[r] = bshfl(v[r], r * 32 + lane, j, 256);
    }
}

// ---------- targets + loss + NMS + histogram-select top-k + decode + finalize ----------
// One block (512 thr = 16 warps) per batch row.
__global__ void __launch_bounds__(512) topk_kernel(const float* __restrict__ sal,
                                                   const float* __restrict__ boundary,
                                                   float* __restrict__ out) {
    __shared__ float s_cp[TT];
    __shared__ int   s_ct[TT];           // gaussian target bits (float >= 0)
    __shared__ int   s_hist[TT];         // value-bucket histogram
    __shared__ u64   s_key[TT];          // staged keys; later merge workspace
    __shared__ u64   s_cand[512];
    __shared__ int   s_valid[MM];
    __shared__ int   s_ci[MM];
    __shared__ int   s_rad[MM];
    __shared__ float s_inv[MM];
    __shared__ float s_win[MM];
    __shared__ float s_cfrac[MM];
    __shared__ float s_red[16];
    __shared__ int   s_B, s_cnt, s_last;

    int b = blockIdx.x, tid = threadIdx.x;
    int w = tid >> 5, lane = tid & 31;

    reinterpret_cast<float4*>(s_cp)[tid] =
        reinterpret_cast<const float4*>(g_center_pred + b * TT)[tid];
#pragma unroll
    for (int r = 0; r < 4; r++) {
        s_ct[tid + 512 * r] = 0;
        s_hist[tid + 512 * r] = 0;
    }
    if (tid == 0) s_cnt = 0;

    if (tid < MM) {
        float b0 = boundary[(b * MM + tid) * 2 + 0];
        float b1 = boundary[(b * MM + tid) * 2 + 1];
        int valid = (b0 != -1.0f);
        float b0c = b0 * 0.5f;
        float b1c = (b1 - 2.0f) * 0.5f;
        float center = fminf((b0c + b1c) * 0.5f, (float)TT - 0.5f);
        float window = b1c - b0c;
        int radius = (int)(window * 0.2f);
        float sigma = ((float)radius + 1.0f) * 0.2f;
        int ci = (int)center;
        s_valid[tid] = valid;
        s_ci[tid]    = ci;
        s_rad[tid]   = radius;
        s_inv[tid]   = 1.0f / (2.0f * sigma * sigma);
        s_win[tid]   = window;
        s_cfrac[tid] = center - (float)ci;
    }
    __syncthreads();

    // ---- gaussian scatter-max: 25 threads per object ----
    {
        int obj = tid / 25, sub = tid - obj * 25;
        if (obj < MM && s_valid[obj]) {
            int rad = s_rad[obj], ci = s_ci[obj];
            float inv = s_inv[obj];
            for (int off = -rad + sub; off <= rad; off += 25) {
                int t = ci + off;
                if (t >= 0 && t < TT) {
                    float g = expf(-(float)(off * off) * inv);
                    atomicMax(&s_ct[t], __float_as_int(g));   // valid: g >= 0
                }
            }
        }
    }
    __syncthreads();

    // ---- center loss + NMS keys + histogram, one pass over t ----
    float cs = 0.f;
    const float* salb = sal + b * TT;
#pragma unroll
    for (int c = 0; c < 4; c++) {
        int t = tid + 512 * c;
        float ct = __int_as_float(s_ct[t]);
        float mask = (salb[t] >= 0.f) ? 1.f : 0.f;
        float cp = s_cp[t];
        float pos = (ct == 1.0f) ? 1.f : 0.f;
        float omc = 1.f - cp;
        float pl = -logf(cp + 1e-12f) * omc * omc * pos;
        float omt = 1.f - ct;
        float o2 = omt * omt;
        float nl = -logf(omc + 1e-12f) * cp * cp * (o2 * o2);
        cs += (pl + nl) * mask;

        float l = (t > 0)      ? s_cp[t - 1] : -INFINITY;
        float rr = (t < TT - 1) ? s_cp[t + 1] : -INFINITY;
        float hmax = fmaxf(cp, fmaxf(l, rr));
        float cpv = (hmax == cp) ? cp : 0.f;
        u64 key = ((u64)__float_as_uint(cpv) << 32) | (unsigned int)(TT - 1 - t);
        s_key[t] = key;
        atomicAdd(&s_hist[(int)(key >> 51)], 1);   // bucket = float_bits >> 19, <= 2032
    }
#pragma unroll
    for (int o = 16; o; o >>= 1) cs += __shfl_xor_sync(0xffffffffu, cs, o);
    if (lane == 0) s_red[w] = cs;

    // ---- window/offset loss: only the <=20 scatter points (warp 1) ----
    if (w == 1) {
        float ws = 0.f, os = 0.f;
        if (lane < MM && s_valid[lane]) {
            bool isLast = true;
#pragma unroll
            for (int jj = 0; jj < MM; jj++)
                if (jj > lane && s_valid[jj] && s_ci[jj] == s_ci[lane]) isLast = false;
            if (isLast) {   // last-write-wins scatter semantics
                int idx = b * TT + s_ci[lane];
                ws = fabsf(g_window_pred[idx] - s_win[lane]);
                os = fabsf(g_offset_pred[idx] - s_cfrac[lane]);
            }
        }
        unsigned vb = __ballot_sync(0xffffffffu, lane < MM && s_valid[lane]);
#pragma unroll
        for (int o = 16; o; o >>= 1) {
            ws += __shfl_xor_sync(0xffffffffu, ws, o);
            os += __shfl_xor_sync(0xffffffffu, os, o);
        }
        if (lane == 0) {
            atomicAdd(&g_acc[1], ws);
            atomicAdd(&g_acc[2], os);
            atomicAdd(&g_acc[3], (float)__popc(vb));
        }
    }
    __syncthreads();
    if (tid == 0) {
        float a = 0.f;
#pragma unroll
        for (int i = 0; i < 16; i++) a += s_red[i];
        atomicAdd(&g_acc[0], a);
    }

    // ---- suffix-scan histogram (warp 0): find bucket B where cum count >= 100 ----
    if (tid < 32) {
        int base = tid * 64;
        int s = 0;
        for (int i = 0; i < 64; i++) s += s_hist[base + i];
        int vsum = s;
#pragma unroll
        for (int o = 1; o < 32; o <<= 1) {
            int t2 = __shfl_down_sync(0xffffffffu, vsum, o);
            if (tid + o < 32) vsum += t2;    // vsum = sum of chunks >= this lane
        }
        int above = vsum - s;                // strictly higher buckets
        if (above < TOPK_N && vsum >= TOPK_N) {   // unique crossing lane
            int cum = above;
            for (int bkt = base + 63; bkt >= base; bkt--) {
                cum += s_hist[bkt];
                if (cum >= TOPK_N) { s_B = bkt; break; }
            }
        }
    }
    __syncthreads();

    // ---- collect candidates: all keys with bucket >= B ----
    int Bv = s_B;
#pragma unroll
    for (int c = 0; c < 4; c++) {
        int t = tid + 512 * c;
        u64 key = s_key[t];
        if ((int)(key >> 51) >= Bv) {
            int p = atomicAdd(&s_cnt, 1);
            if (p < 512) s_cand[p] = key;
        }
    }
    __syncthreads();
    int N = s_cnt;
    bool fast = (N <= 512) && (Bv >= 1);   // B>=1 => every candidate key > 0-pad

    if (fast) {
        // 4 warps sort 512 (padded) -> exact sorted top-128 in s_key[0..127]
        u64 v[4];
        if (w < 4) {
#pragma unroll
            for (int r = 0; r < 4; r++) {
                int i = w * 128 + r * 32 + lane;
                v[r] = (i < N) ? s_cand[i] : 0ull;
            }
            warp_sort128(v, lane);
        }
        for (int m = 0; m < 2; m++) {
            int h = 1 << m;
            if (w < 4 && (w & (h - 1)) == 0) {
#pragma unroll
                for (int r = 0; r < 4; r++) s_key[w * 128 + r * 32 + lane] = v[r];
            }
            __syncthreads();
            if (w < 4 && (w & (2 * h - 1)) == 0) {
                int p = w + h;
#pragma unroll
                for (int r = 0; r < 4; r++) {
                    u64 bv = s_key[p * 128 + 127 - (r * 32 + lane)];
                    v[r] = v[r] > bv ? v[r] : bv;
                }
                warp_merge128(v, lane);
            }
            __syncthreads();
        }
        if (w == 0) {
#pragma unroll
            for (int r = 0; r < 4; r++) s_key[r * 32 + lane] = v[r];
        }
        __syncthreads();
    } else {
        // fallback: full 16-warp sort of all 2048 keys (exact, rare)
        u64 v[4];
#pragma unroll
        for (int r = 0; r < 4; r++) v[r] = s_key[w * 128 + r * 32 + lane];
        warp_sort128(v, lane);
        for (int m = 0; m < 4; m++) {
            int h = 1 << m;
            if ((w & (h - 1)) == 0) {
#pragma unroll
                for (int r = 0; r < 4; r++) s_key[w * 128 + r * 32 + lane] = v[r];
            }
            __syncthreads();
            if ((w & (2 * h - 1)) == 0) {
                int p = w + h;
#pragma unroll
                for (int r = 0; r < 4; r++) {
                    u64 bv = s_key[p * 128 + 127 - (r * 32 + lane)];
                    v[r] = v[r] > bv ? v[r] : bv;
                }
                warp_merge128(v, lane);
            }
            __syncthreads();
        }
        if (w == 0) {
#pragma unroll
            for (int r = 0; r < 4; r++) s_key[r * 32 + lane] = v[r];
        }
        __syncthreads();
    }

    if (tid < TOPK_N) {
        u64 key = s_key[tid];
        float score = __uint_as_float((unsigned int)(key >> 32));
        int idx = TT - 1 - (int)(key & 0xffffffffu);
        float off = fmaxf(g_offset_pred[b * TT + idx], 0.f);
        float center = (float)idx + off;
        float window = fmaxf(g_window_pred[b * TT + idx], 0.f);
        float lo = fminf(fmaxf(center - window * 0.5f, 0.f), (float)(TT - 1)) * 2.0f;
        float hi = fminf(fmaxf(center + window * 0.5f, 0.f), (float)(TT - 1)) * 2.0f + 2.0f;
        float* o = out + ((size_t)b * TOPK_N + tid) * 3;
        o[0] = lo; o[1] = hi; o[2] = score;
    }

    // ---- finalize: last block writes losses, then resets accumulators ----
    __syncthreads();
    if (tid == 0) {
        __threadfence();
        unsigned int old = atomicAdd(&g_ticket, 1u);
        s_last = (old == BB - 1) ? 1 : 0;
    }
    __syncthreads();
    if (s_last && tid == 0) {
        __threadfence();
        float avg = g_acc[3];
        out[BB * TOPK_N * 3 + 0] = g_acc[0] / avg;
        out[BB * TOPK_N * 3 + 1] = 0.1f * g_acc[1] / avg;
        out[BB * TOPK_N * 3 + 2] = g_acc[2] / avg;
        g_acc[0] = 0.f; g_acc[1] = 0.f; g_acc[2] = 0.f; g_acc[3] = 0.f;
        g_ticket = 0;   // leave state zeroed for the next (graph-replayed) run
    }
}

extern "C" void kernel_launch(void* const* d_in, const int* in_sizes, int n_in,
                              void* d_out, int out_size) {
    const float* x        = (const float*)d_in[0];
    const float* w_center = (const float*)d_in[1];
    const float* b_center = (const float*)d_in[2];
    const float* w_window = (const float*)d_in[3];
    const float* b_window = (const float*)d_in[4];
    const float* w_offset = (const float*)d_in[5];
    const float* b_offset = (const float*)d_in[6];
    const float* saliency = (const float*)d_in[7];
    const float* boundary = (const float*)d_in[8];
    float* out = (float*)d_out;

    proj_kernel<<<(BB * TT) / 16, 256>>>(x, w_center, b_center, w_window, b_window,
                                         w_offset, b_offset, saliency);
    topk_kernel<<<BB, 512>>>(saliency, boundary, out);
}

// round 14
// speedup vs baseline: 2.0594x; 1.0384x over previous
#include <cuda_runtime.h>
#include <math.h>

#define BB 64
#define TT 2048
#define DD 256
#define MM 20
#define TOPK_N 100

typedef unsigned long long u64;

// ---------- scratch (no allocations allowed) ----------
__device__ float g_center_pred[BB * TT];
__device__ float g_window_pred[BB * TT];
__device__ float g_offset_pred[BB * TT];
__device__ float g_acc[4];          // zero-init; finalize re-zeros after use
__device__ unsigned int g_ticket;   // ditto

// ---------- pure 3-way GEMV + sigmoid + mask ----------
__global__ void __launch_bounds__(256) proj_kernel(
        const float* __restrict__ x,
        const float* __restrict__ wc, const float* __restrict__ bc,
        const float* __restrict__ ww, const float* __restrict__ bw,
        const float* __restrict__ wo, const float* __restrict__ bo,
        const float* __restrict__ sal) {
    __shared__ float s_w[3 * DD];
    int tid = threadIdx.x;
    for (int i = tid; i < 3 * DD; i += 256) {
        s_w[i] = (i < DD) ? wc[i] : (i < 2 * DD) ? ww[i - DD] : wo[i - 2 * DD];
    }
    __syncthreads();

    int w = tid >> 5, lane = tid & 31;
    size_t pair = (size_t)blockIdx.x * 8 + w;
    size_t row0 = pair * 2, row1 = row0 + 1;
    const float4* x0 = reinterpret_cast<const float4*>(x + row0 * DD);
    const float4* x1 = reinterpret_cast<const float4*>(x + row1 * DD);
    const float4* w0 = reinterpret_cast<const float4*>(s_w);
    const float4* w1 = reinterpret_cast<const float4*>(s_w + DD);
    const float4* w2 = reinterpret_cast<const float4*>(s_w + 2 * DD);

    float4 p0 = __ldcs(&x0[lane]);
    float4 p1 = __ldcs(&x0[lane + 32]);
    float4 q0 = __ldcs(&x1[lane]);
    float4 q1 = __ldcs(&x1[lane + 32]);

    float4 a0 = w0[lane], a1 = w0[lane + 32];
    float4 b0 = w1[lane], b1 = w1[lane + 32];
    float4 c0 = w2[lane], c1 = w2[lane + 32];

    float sc0 = p0.x*a0.x + p0.y*a0.y + p0.z*a0.z + p0.w*a0.w
              + p1.x*a1.x + p1.y*a1.y + p1.z*a1.z + p1.w*a1.w;
    float sw0 = p0.x*b0.x + p0.y*b0.y + p0.z*b0.z + p0.w*b0.w
              + p1.x*b1.x + p1.y*b1.y + p1.z*b1.z + p1.w*b1.w;
    float so0 = p0.x*c0.x + p0.y*c0.y + p0.z*c0.z + p0.w*c0.w
              + p1.x*c1.x + p1.y*c1.y + p1.z*c1.z + p1.w*c1.w;
    float sc1 = q0.x*a0.x + q0.y*a0.y + q0.z*a0.z + q0.w*a0.w
              + q1.x*a1.x + q1.y*a1.y + q1.z*a1.z + q1.w*a1.w;
    float sw1 = q0.x*b0.x + q0.y*b0.y + q0.z*b0.z + q0.w*b0.w
              + q1.x*b1.x + q1.y*b1.y + q1.z*b1.z + q1.w*b1.w;
    float so1 = q0.x*c0.x + q0.y*c0.y + q0.z*c0.z + q0.w*c0.w
              + q1.x*c1.x + q1.y*c1.y + q1.z*c1.z + q1.w*c1.w;

#pragma unroll
    for (int o = 16; o; o >>= 1) {
        sc0 += __shfl_xor_sync(0xffffffffu, sc0, o);
        sw0 += __shfl_xor_sync(0xffffffffu, sw0, o);
        so0 += __shfl_xor_sync(0xffffffffu, so0, o);
        sc1 += __shfl_xor_sync(0xffffffffu, sc1, o);
        sw1 += __shfl_xor_sync(0xffffffffu, sw1, o);
        so1 += __shfl_xor_sync(0xffffffffu, so1, o);
    }
    if (lane == 0) {
        float mask = (sal[row0] >= 0.f) ? 1.f : 0.f;
        g_center_pred[row0] = (1.f / (1.f + expf(-(sc0 + bc[0])))) * mask;
        g_window_pred[row0] = sw0 + bw[0];
        g_offset_pred[row0] = so0 + bo[0];
    } else if (lane == 1) {
        float mask = (sal[row1] >= 0.f) ? 1.f : 0.f;
        g_center_pred[row1] = (1.f / (1.f + expf(-(sc1 + bc[0])))) * mask;
        g_window_pred[row1] = sw1 + bw[0];
        g_offset_pred[row1] = so1 + bo[0];
    }
}

// bitonic compare-exchange via warp shuffle (j <= 16)
__device__ __forceinline__ u64 bshfl(u64 v, int i, int j, int k) {
    u64 pv = __shfl_xor_sync(0xffffffffu, v, j);
    bool lower = ((i & j) == 0);
    bool up = ((i & k) == 0);
    u64 mx = v > pv ? v : pv;
    u64 mn = v > pv ? pv : v;
    return (lower == up) ? mx : mn;
}

__device__ __forceinline__ void cxpair(u64& a, u64& b, bool up) {
    u64 mx = a > b ? a : b;
    u64 mn = a > b ? b : a;
    a = up ? mx : mn;
    b = up ? mn : mx;
}

__device__ __forceinline__ void warp_sort128(u64 v[4], int lane) {
#pragma unroll
    for (int k = 2; k <= 128; k <<= 1) {
#pragma unroll
        for (int j = 64; j > 0; j >>= 1) {
            if (j >= k) continue;
            if (j >= 32) {
                int s = j >> 5;
#pragma unroll
                for (int r = 0; r < 4; r++) {
                    if ((r & s) == 0) cxpair(v[r], v[r | s], ((r * 32 + lane) & k) == 0);
                }
            } else {
#pragma unroll
                for (int r = 0; r < 4; r++) v[r] = bshfl(v[r], r * 32 + lane, j, k);
            }
        }
    }
}

__device__ __forceinline__ void warp_merge128(u64 v[4], int lane) {
    cxpair(v[0], v[2], true);
    cxpair(v[1], v[3], true);
    cxpair(v[0], v[1], true);
    cxpair(v[2], v[3], true);
#pragma unroll
    for (int j = 16; j > 0; j >>= 1) {
#pragma unroll
        for (int r = 0; r < 4; r++) v[r] = bshfl(v[r], r * 32 + lane, j, 256);
    }
}

// ---------- targets + loss + NMS + histogram-select top-k + decode + finalize ----------
// One block (512 thr) per batch; thread tid owns t in [4*tid, 4*tid+4).
__global__ void __launch_bounds__(512) topk_kernel(const float* __restrict__ sal,
                                                   const float* __restrict__ boundary,
                                                   float* __restrict__ out) {
    __shared__ float s_cp[TT];
    __shared__ int   s_ct[TT];
    __shared__ int   s_hist[TT];
    __shared__ u64   s_key[TT];          // candidates [0..511] / fallback workspace
    __shared__ int   s_valid[MM];
    __shared__ int   s_ci[MM];
    __shared__ int   s_rad[MM];
    __shared__ float s_inv[MM];
    __shared__ float s_win[MM];
    __shared__ float s_cfrac[MM];
    __shared__ float s_red[16];
    __shared__ int   s_wsum[16], s_wabove[16];
    __shared__ int   s_B, s_cnt, s_last;

    int b = blockIdx.x, tid = threadIdx.x;
    int w = tid >> 5, lane = tid & 31;

    reinterpret_cast<float4*>(s_cp)[tid] =
        reinterpret_cast<const float4*>(g_center_pred + b * TT)[tid];
    reinterpret_cast<int4*>(s_ct)[tid]   = make_int4(0, 0, 0, 0);
    reinterpret_cast<int4*>(s_hist)[tid] = make_int4(0, 0, 0, 0);
    if (tid == 0) { s_cnt = 0; s_B = 0; }

    if (tid < MM) {
        float b0 = boundary[(b * MM + tid) * 2 + 0];
        float b1 = boundary[(b * MM + tid) * 2 + 1];
        int valid = (b0 != -1.0f);
        float b0c = b0 * 0.5f;
        float b1c = (b1 - 2.0f) * 0.5f;
        float center = fminf((b0c + b1c) * 0.5f, (float)TT - 0.5f);
        float window = b1c - b0c;
        int radius = (int)(window * 0.2f);
        float sigma = ((float)radius + 1.0f) * 0.2f;
        int ci = (int)center;
        s_valid[tid] = valid;
        s_ci[tid]    = ci;
        s_rad[tid]   = radius;
        s_inv[tid]   = 1.0f / (2.0f * sigma * sigma);
        s_win[tid]   = window;
        s_cfrac[tid] = center - (float)ci;
    }
    __syncthreads();

    // ---- gaussian scatter-max: 25 threads per object ----
    {
        int obj = tid / 25, sub = tid - obj * 25;
        if (obj < MM && s_valid[obj]) {
            int rad = s_rad[obj], ci = s_ci[obj];
            float inv = s_inv[obj];
            for (int off = -rad + sub; off <= rad; off += 25) {
                int t = ci + off;
                if (t >= 0 && t < TT) {
                    float g = expf(-(float)(off * off) * inv);
                    atomicMax(&s_ct[t], __float_as_int(g));
                }
            }
        }
    }
    __syncthreads();

    // ---- loss + NMS keys (registers) + positive-only histogram ----
    float4 salv = reinterpret_cast<const float4*>(sal + b * TT)[tid];
    float4 cpq  = reinterpret_cast<float4*>(s_cp)[tid];
    int4   ctq  = reinterpret_cast<int4*>(s_ct)[tid];
    float cpl = (tid > 0)   ? s_cp[4 * tid - 1] : -INFINITY;
    float cpr = (tid < 511) ? s_cp[4 * tid + 4] : -INFINITY;

    float cpa[4] = {cpq.x, cpq.y, cpq.z, cpq.w};
    float nl4[4] = {cpl, cpq.x, cpq.y, cpq.z};
    float nr4[4] = {cpq.y, cpq.z, cpq.w, cpr};
    int   cta[4] = {ctq.x, ctq.y, ctq.z, ctq.w};
    float sa4[4] = {salv.x, salv.y, salv.z, salv.w};
    u64 key[4];

    float cs = 0.f;
#pragma unroll
    for (int c = 0; c < 4; c++) {
        float cp = cpa[c];
        float ct = __int_as_float(cta[c]);
        float mask = (sa4[c] >= 0.f) ? 1.f : 0.f;
        float pos = (ct == 1.0f) ? 1.f : 0.f;
        float omc = 1.f - cp;
        float pl = -logf(cp + 1e-12f) * omc * omc * pos;
        float omt = 1.f - ct;
        float o2 = omt * omt;
        float nl = -logf(omc + 1e-12f) * cp * cp * (o2 * o2);
        cs += (pl + nl) * mask;

        float hmax = fmaxf(cp, fmaxf(nl4[c], nr4[c]));
        float cpv = (hmax == cp) ? cp : 0.f;
        int t = 4 * tid + c;
        key[c] = ((u64)__float_as_uint(cpv) << 32) | (unsigned int)(TT - 1 - t);
        if (cpv > 0.f) atomicAdd(&s_hist[__float_as_uint(cpv) >> 19], 1);
    }
#pragma unroll
    for (int o = 16; o; o >>= 1) cs += __shfl_xor_sync(0xffffffffu, cs, o);
    if (lane == 0) s_red[w] = cs;

    // ---- window/offset loss: only the <=20 scatter points (warp 1) ----
    if (w == 1) {
        float ws = 0.f, os = 0.f;
        if (lane < MM && s_valid[lane]) {
            bool isLast = true;
#pragma unroll
            for (int jj = 0; jj < MM; jj++)
                if (jj > lane && s_valid[jj] && s_ci[jj] == s_ci[lane]) isLast = false;
            if (isLast) {
                int idx = b * TT + s_ci[lane];
                ws = fabsf(g_window_pred[idx] - s_win[lane]);
                os = fabsf(g_offset_pred[idx] - s_cfrac[lane]);
            }
        }
        unsigned vb = __ballot_sync(0xffffffffu, lane < MM && s_valid[lane]);
#pragma unroll
        for (int o = 16; o; o >>= 1) {
            ws += __shfl_xor_sync(0xffffffffu, ws, o);
            os += __shfl_xor_sync(0xffffffffu, os, o);
        }
        if (lane == 0) {
            atomicAdd(&g_acc[1], ws);
            atomicAdd(&g_acc[2], os);
            atomicAdd(&g_acc[3], (float)__popc(vb));
        }
    }
    __syncthreads();

    // ---- parallel suffix-scan of histogram: find bucket B (cum from top >= 100) ----
    int4 hq = reinterpret_cast<int4*>(s_hist)[tid];
    int mysum = hq.x + hq.y + hq.z + hq.w;
    int p = mysum;
#pragma unroll
    for (int o = 1; o < 32; o <<= 1) {
        int t2 = __shfl_down_sync(0xffffffffu, p, o);
        if (lane + o < 32) p += t2;       // p = suffix-incl sum over lanes >= lane
    }
    if (lane == 0) s_wsum[w] = p;
    __syncthreads();
    if (tid < 16) {
        int vv = s_wsum[tid];
        int q = vv;
#pragma unroll
        for (int o = 1; o < 16; o <<= 1) {
            int t2 = __shfl_down_sync(0xffffu, q, o);
            if (tid + o < 16) q += t2;
        }
        s_wabove[tid] = q - vv;           // totals of warps > tid
        // fold the 16 center-loss partials here too
        float rr = s_red[tid];
#pragma unroll
        for (int o = 1; o < 16; o <<= 1) rr += __shfl_down_sync(0xffffu, rr, o);
        if (tid == 0) atomicAdd(&g_acc[0], rr);
    }
    __syncthreads();
    {
        int above = s_wabove[w] + (p - mysum);
        if (above < TOPK_N && above + mysum >= TOPK_N) {  // unique crossing thread
            int cum = above, Bf;
            if      ((cum += hq.w) >= TOPK_N) Bf = 4 * tid + 3;
            else if ((cum += hq.z) >= TOPK_N) Bf = 4 * tid + 2;
            else if ((cum += hq.y) >= TOPK_N) Bf = 4 * tid + 1;
            else                              Bf = 4 * tid;
            s_B = Bf;
        }
    }
    __syncthreads();

    // ---- candidate collection: warp-aggregated append ----
    int Bv = s_B;
#pragma unroll
    for (int c = 0; c < 4; c++) {
        bool cand = ((unsigned int)(key[c] >> 32) != 0u) && ((int)(key[c] >> 51) >= Bv);
        unsigned bal = __ballot_sync(0xffffffffu, cand);
        int base = 0;
        if (lane == 0) base = atomicAdd(&s_cnt, __popc(bal));
        base = __shfl_sync(0xffffffffu, base, 0);
        int pos = base + __popc(bal & ((1u << lane) - 1u));
        if (cand && pos < 512) s_key[pos] = key[c];
    }
    __syncthreads();
    int N = s_cnt;
    bool fast = (N <= 512) && (Bv >= 1);

    if (fast) {
        u64 v[4];
        if (w < 4) {
#pragma unroll
            for (int r = 0; r < 4; r++) {
                int i = w * 128 + r * 32 + lane;
                v[r] = (i < N) ? s_key[i] : 0ull;
            }
            warp_sort128(v, lane);
        }
        for (int m = 0; m < 2; m++) {
            int h = 1 << m;
            if (w < 4 && (w & (h - 1)) == 0) {
#pragma unroll
                for (int r = 0; r < 4; r++) s_key[w * 128 + r * 32 + lane] = v[r];
            }
            __syncthreads();
            if (w < 4 && (w & (2 * h - 1)) == 0) {
                int pp = w + h;
#pragma unroll
                for (int r = 0; r < 4; r++) {
                    u64 bv = s_key[pp * 128 + 127 - (r * 32 + lane)];
                    v[r] = v[r] > bv ? v[r] : bv;
                }
                warp_merge128(v, lane);
            }
            __syncthreads();
        }
        if (w == 0) {
#pragma unroll
            for (int r = 0; r < 4; r++) s_key[r * 32 + lane] = v[r];
        }
        __syncthreads();
    } else {
        // fallback: stage all keys, full 16-warp sort (exact, rare)
#pragma unroll
        for (int c = 0; c < 4; c++) s_key[4 * tid + c] = key[c];
        __syncthreads();
        u64 v[4];
#pragma unroll
        for (int r = 0; r < 4; r++) v[r] = s_key[w * 128 + r * 32 + lane];
        warp_sort128(v, lane);
        for (int m = 0; m < 4; m++) {
            int h = 1 << m;
            if ((w & (h - 1)) == 0) {
#pragma unroll
                for (int r = 0; r < 4; r++) s_key[w * 128 + r * 32 + lane] = v[r];
            }
            __syncthreads();
            if ((w & (2 * h - 1)) == 0) {
                int pp = w + h;
#pragma unroll
                for (int r = 0; r < 4; r++) {
                    u64 bv = s_key[pp * 128 + 127 - (r * 32 + lane)];
                    v[r] = v[r] > bv ? v[r] : bv;
                }
                warp_merge128(v, lane);
            }
            __syncthreads();
        }
        if (w == 0) {
#pragma unroll
            for (int r = 0; r < 4; r++) s_key[r * 32 + lane] = v[r];
        }
        __syncthreads();
    }

    if (tid < TOPK_N) {
        u64 k2 = s_key[tid];
        float score = __uint_as_float((unsigned int)(k2 >> 32));
        int idx = TT - 1 - (int)(k2 & 0xffffffffu);
        float off = fmaxf(g_offset_pred[b * TT + idx], 0.f);
        float center = (float)idx + off;
        float window = fmaxf(g_window_pred[b * TT + idx], 0.f);
        float lo = fminf(fmaxf(center - window * 0.5f, 0.f), (float)(TT - 1)) * 2.0f;
        float hi = fminf(fmaxf(center + window * 0.5f, 0.f), (float)(TT - 1)) * 2.0f + 2.0f;
        float* o = out + ((size_t)b * TOPK_N + tid) * 3;
        o[0] = lo; o[1] = hi; o[2] = score;
    }

    // ---- finalize: last block writes losses, then resets accumulators ----
    __syncthreads();
    if (tid == 0) {
        __threadfence();
        unsigned int old = atomicAdd(&g_ticket, 1u);
        s_last = (old == BB - 1) ? 1 : 0;
    }
    __syncthreads();
    if (s_last && tid == 0) {
        __threadfence();
        float avg = g_acc[3];
        out[BB * TOPK_N * 3 + 0] = g_acc[0] / avg;
        out[BB * TOPK_N * 3 + 1] = 0.1f * g_acc[1] / avg;
        out[BB * TOPK_N * 3 + 2] = g_acc[2] / avg;
        g_acc[0] = 0.f; g_acc[1] = 0.f; g_acc[2] = 0.f; g_acc[3] = 0.f;
        g_ticket = 0;
    }
}

extern "C" void kernel_launch(void* const* d_in, const int* in_sizes, int n_in,
                              void* d_out, int out_size) {
    const float* x        = (const float*)d_in[0];
    const float* w_center = (const float*)d_in[1];
    const float* b_center = (const float*)d_in[2];
    const float* w_window = (const float*)d_in[3];
    const float* b_window = (const float*)d_in[4];
    const float* w_offset = (const float*)d_in[5];
    const float* b_offset = (const float*)d_in[6];
    const float* saliency = (const float*)d_in[7];
    const float* boundary = (const float*)d_in[8];
    float* out = (float*)d_out;

    proj_kernel<<<(BB * TT) / 16, 256>>>(x, w_center, b_center, w_window, b_window,
                                         w_offset, b_offset, saliency);
    topk_kernel<<<BB, 512>>>(saliency, boundary, out);
}